// round 1
// baseline (speedup 1.0000x reference)
#include <cuda_runtime.h>
#include <cuda_bf16.h>

// Problem constants
#define BB    4
#define NQ    384
#define NK    384
#define DE    64     // d_equi
#define DMSG  64
#define DFF   256
#define DOUT  64
#define DINV  256    // d_qinv == d_kvinv

// Scratch: A_q[b,q,ff] = q_msg @ W1[0:64,:] + b1 ; A_k[b,k,ff] = k_msg @ W1[64:128,:]
__device__ float g_Aq[BB * NQ * DFF];
__device__ float g_Ak[BB * NK * DFF];

// ---------------------------------------------------------------------------
// Prelude: per-row message projection + fold through first-layer weight slices
// grid = BB*(NQ+NK) blocks, 256 threads
// ---------------------------------------------------------------------------
__global__ void __launch_bounds__(256) prelude_kernel(
    const float* __restrict__ q_inv, const float* __restrict__ k_inv,
    const float* __restrict__ Wq, const float* __restrict__ bq,
    const float* __restrict__ Wk, const float* __restrict__ bk,
    const float* __restrict__ W1, const float* __restrict__ b1)
{
    int idx = blockIdx.x;
    bool isQ = idx < BB * NQ;
    int bn = isQ ? idx : idx - BB * NQ;

    const float* inv  = isQ ? (q_inv + bn * DINV) : (k_inv + bn * DINV);
    const float* W    = isQ ? Wq : Wk;
    const float* bias = isQ ? bq : bk;
    const float* W1s  = isQ ? W1 : (W1 + DMSG * DFF);  // rows 0:64 (q) or 64:128 (k)
    float* A          = isQ ? (g_Aq + bn * DFF) : (g_Ak + bn * DFF);

    __shared__ float s_inv[DINV];
    __shared__ float s_part[4][DMSG];
    __shared__ float s_msg[DMSG];

    int tid = threadIdx.x;
    s_inv[tid] = inv[tid];
    __syncthreads();

    // msg[m] = sum_i inv[i]*W[i,m] + bias[m]; split the 256-long reduction 4 ways
    int m = tid & 63;
    int g = tid >> 6;
    float acc = 0.f;
    #pragma unroll 8
    for (int i = g * 64; i < g * 64 + 64; i++)
        acc = fmaf(s_inv[i], W[i * DMSG + m], acc);
    s_part[g][m] = acc;
    __syncthreads();
    if (tid < DMSG)
        s_msg[tid] = s_part[0][tid] + s_part[1][tid] + s_part[2][tid] + s_part[3][tid] + bias[tid];
    __syncthreads();

    // A[ff] = (isQ ? b1[ff] : 0) + sum_m msg[m] * W1s[m, ff]
    float a = isQ ? b1[tid] : 0.f;
    #pragma unroll 8
    for (int mm = 0; mm < DMSG; mm++)
        a = fmaf(s_msg[mm], W1s[mm * DFF + tid], a);
    A[tid] = a;
}

// ---------------------------------------------------------------------------
// Main pairwise kernel: one block = 8 q x 8 k = 64 pairs.
// Phase 1: load equi tiles + A tiles; compute dot/dist -> sdd[64][128]
// Phase 2: GEMM1 pre[64,256] = sdd @ W1[128:256,:]  (thread tile 4x16)
// Phase 3: h = silu(pre + Aq + Ak) -> smem
// Phase 4: GEMM2 out[64,64] = h @ W2 + b2          (thread tile 4x4)
// ---------------------------------------------------------------------------
__device__ __forceinline__ float silu_f(float x) {
    return x * (1.f / (1.f + __expf(-x)));
}

#define SDD_LD 132   // 128 + 4 pad
#define SH_LD  260   // 256 + 4 pad

__global__ void __launch_bounds__(256) pair_kernel(
    const float* __restrict__ q_equi, const float* __restrict__ k_equi,
    const float* __restrict__ W1, const float* __restrict__ W2,
    const float* __restrict__ b2, float* __restrict__ out)
{
    extern __shared__ float s[];
    float* sqe = s;                 // 8*3*64       = 1536
    float* ske = sqe + 1536;        //              = 1536
    float* saq = ske + 1536;        // 8*256        = 2048
    float* sak = saq + 2048;        //              = 2048
    float* sdd = sak + 2048;        // 64*132       = 8448
    float* sw  = sdd + 8448;        // 16*256       = 4096  (reused for W2 chunks)
    float* sh  = sw  + 4096;        // 64*260       = 16640
    // total 36352 floats = 145408 bytes

    int b  = blockIdx.z;
    int q0 = blockIdx.y * 8;
    int k0 = blockIdx.x * 8;
    int tid = threadIdx.x;
    int tx = tid & 15;
    int ty = tid >> 4;

    // ---- Phase 1: stage inputs ----
    const float* qe = q_equi + (size_t)(b * NQ + q0) * (3 * DE);
    const float* ke = k_equi + (size_t)(b * NK + k0) * (3 * DE);
    #pragma unroll
    for (int i = tid; i < 1536; i += 256) { sqe[i] = qe[i]; ske[i] = ke[i]; }
    const float* aq = g_Aq + (size_t)(b * NQ + q0) * DFF;
    const float* ak = g_Ak + (size_t)(b * NK + k0) * DFF;
    #pragma unroll
    for (int i = tid; i < 2048; i += 256) { saq[i] = aq[i]; sak[i] = ak[i]; }
    __syncthreads();

    // ---- dot & dist per (pair, channel) ----
    {
        int e  = tid & 63;
        int p0 = tid >> 6;           // 0..3
        #pragma unroll
        for (int i = 0; i < 16; i++) {
            int p  = p0 * 16 + i;    // 0..63
            int qi = p >> 3, ki = p & 7;
            float d = 0.f, s2 = 0.f;
            #pragma unroll
            for (int c = 0; c < 3; c++) {
                float a = sqe[(qi * 3 + c) * DE + e];
                float g = ske[(ki * 3 + c) * DE + e];
                d  = fmaf(a, g, d);
                float df = a - g;
                s2 = fmaf(df, df, s2);
            }
            sdd[p * SDD_LD + e]      = d;
            sdd[p * SDD_LD + 64 + e] = sqrtf(s2);
        }
    }
    __syncthreads();

    // ---- Phase 2: GEMM1 — pre[64,256] = sdd[64,128] @ W1[128:256, 0:256] ----
    float acc[4][16];
    #pragma unroll
    for (int i = 0; i < 4; i++)
        #pragma unroll
        for (int j = 0; j < 16; j++) acc[i][j] = 0.f;

    const float* W1d = W1 + 128 * DFF;  // rows 128..255 (dot then dist slices)
    for (int kc = 0; kc < 8; kc++) {
        const float* src = W1d + kc * 16 * DFF;     // 16x256 chunk, contiguous
        #pragma unroll
        for (int i = tid * 4; i < 4096; i += 1024)
            *(float4*)(sw + i) = *(const float4*)(src + i);
        __syncthreads();
        #pragma unroll
        for (int kk = 0; kk < 16; kk++) {
            float a[4];
            #pragma unroll
            for (int i = 0; i < 4; i++)
                a[i] = sdd[(ty * 4 + i) * SDD_LD + kc * 16 + kk];
            #pragma unroll
            for (int j = 0; j < 4; j++) {
                float4 w4 = *(const float4*)(sw + kk * 256 + tx * 4 + 64 * j);
                #pragma unroll
                for (int i = 0; i < 4; i++) {
                    acc[i][j * 4 + 0] = fmaf(a[i], w4.x, acc[i][j * 4 + 0]);
                    acc[i][j * 4 + 1] = fmaf(a[i], w4.y, acc[i][j * 4 + 1]);
                    acc[i][j * 4 + 2] = fmaf(a[i], w4.z, acc[i][j * 4 + 2]);
                    acc[i][j * 4 + 3] = fmaf(a[i], w4.w, acc[i][j * 4 + 3]);
                }
            }
        }
        __syncthreads();
    }

    // ---- Phase 3: add A_q + A_k, SiLU, stage h ----
    #pragma unroll
    for (int i = 0; i < 4; i++) {
        int p = ty * 4 + i;
        int qi = p >> 3, ki = p & 7;
        #pragma unroll
        for (int j = 0; j < 4; j++) {
            int n = tx * 4 + 64 * j;
            float4 v;
            v.x = silu_f(acc[i][j * 4 + 0] + saq[qi * 256 + n + 0] + sak[ki * 256 + n + 0]);
            v.y = silu_f(acc[i][j * 4 + 1] + saq[qi * 256 + n + 1] + sak[ki * 256 + n + 1]);
            v.z = silu_f(acc[i][j * 4 + 2] + saq[qi * 256 + n + 2] + sak[ki * 256 + n + 2]);
            v.w = silu_f(acc[i][j * 4 + 3] + saq[qi * 256 + n + 3] + sak[ki * 256 + n + 3]);
            *(float4*)(sh + p * SH_LD + n) = v;
        }
    }
    __syncthreads();

    // ---- Phase 4: GEMM2 — out[64,64] = h[64,256] @ W2[256,64] ----
    float acc2[4][4];
    #pragma unroll
    for (int i = 0; i < 4; i++)
        #pragma unroll
        for (int j = 0; j < 4; j++) acc2[i][j] = 0.f;

    for (int kc = 0; kc < 16; kc++) {
        const float* src = W2 + kc * 16 * DOUT;     // 16x64 chunk
        if (tid * 4 < 1024)
            *(float4*)(sw + tid * 4) = *(const float4*)(src + tid * 4);
        __syncthreads();
        #pragma unroll
        for (int kk = 0; kk < 16; kk++) {
            float a[4];
            #pragma unroll
            for (int i = 0; i < 4; i++)
                a[i] = sh[(ty * 4 + i) * SH_LD + kc * 16 + kk];
            float4 w4 = *(const float4*)(sw + kk * 64 + tx * 4);
            #pragma unroll
            for (int i = 0; i < 4; i++) {
                acc2[i][0] = fmaf(a[i], w4.x, acc2[i][0]);
                acc2[i][1] = fmaf(a[i], w4.y, acc2[i][1]);
                acc2[i][2] = fmaf(a[i], w4.z, acc2[i][2]);
                acc2[i][3] = fmaf(a[i], w4.w, acc2[i][3]);
            }
        }
        __syncthreads();
    }

    // ---- Epilogue: + b2, write out ----
    float4 bb = *(const float4*)(b2 + tx * 4);
    #pragma unroll
    for (int i = 0; i < 4; i++) {
        int p = ty * 4 + i;
        int qi = p >> 3, ki = p & 7;
        float4 v;
        v.x = acc2[i][0] + bb.x;
        v.y = acc2[i][1] + bb.y;
        v.z = acc2[i][2] + bb.z;
        v.w = acc2[i][3] + bb.w;
        size_t off = ((size_t)(b * NQ + q0 + qi) * NK + (k0 + ki)) * DOUT + tx * 4;
        *(float4*)(out + off) = v;
    }
}

// ---------------------------------------------------------------------------
extern "C" void kernel_launch(void* const* d_in, const int* in_sizes, int n_in,
                              void* d_out, int out_size)
{
    const float* q_equi = (const float*)d_in[0];
    const float* q_inv  = (const float*)d_in[1];
    const float* k_equi = (const float*)d_in[2];
    const float* k_inv  = (const float*)d_in[3];
    const float* Wq     = (const float*)d_in[4];
    const float* bq     = (const float*)d_in[5];
    const float* Wk     = (const float*)d_in[6];
    const float* bk     = (const float*)d_in[7];
    const float* W1     = (const float*)d_in[8];
    const float* b1     = (const float*)d_in[9];
    const float* W2     = (const float*)d_in[10];
    const float* b2     = (const float*)d_in[11];
    float* out = (float*)d_out;

    // 145408 bytes of dynamic smem for the pair kernel (idempotent; capture-safe)
    cudaFuncSetAttribute(pair_kernel, cudaFuncAttributeMaxDynamicSharedMemorySize, 145408);

    prelude_kernel<<<BB * (NQ + NK), 256>>>(q_inv, k_inv, Wq, bq, Wk, bk, W1, b1);

    dim3 grid(NK / 8, NQ / 8, BB);
    pair_kernel<<<grid, 256, 145408>>>(q_equi, k_equi, W1, W2, b2, out);
}

// round 3
// speedup vs baseline: 4.2663x; 4.2663x over previous
#include <cuda_runtime.h>
#include <cuda_fp16.h>
#include <cstdint>

// ---------------- problem constants ----------------
#define BB    4
#define NQ    384
#define NK    384
#define DE    64
#define DMSG  64
#define DFF   256
#define DOUT  64
#define DINV  256

#define TQ    16
#define TK    8
#define TM    128          // pairs per tile

#define LDA   136          // half pitch for A / W1 chunk tiles (k=128 + 8 pad)
#define LDH   72           // half pitch for h / W2 chunk tiles (k=64 + 8 pad)

// ---------------- device scratch ----------------
__device__ float g_Aq[BB * NQ * DFF];
__device__ float g_Ak[BB * NK * DFF];
__device__ __align__(16) __half g_W1T[DFF * LDA];   // [n=256][k pitch 136] fp16
__device__ __align__(16) __half g_W2T[DOUT * 264];  // [n=64][k pitch 264] fp16

// ---------------- SMEM map (bytes) ----------------
#define OFF_SA   0        // 128*136*2 = 34816   A (dot|dist) fp16
#define OFF_AQ   34816    // 16*256*4  = 16384   A_q fp32
#define OFF_AK   51200    //  8*256*4  =  8192   A_k fp32
#define OFF_W1C  59392    // 64*136*2  = 17408   W1T chunk (aliased: qe staging)
#define OFF_H    76800    // 128*72*2  = 18432   h chunk fp16 (aliased: ke staging)
#define OFF_W2C  95232    // 64*72*2   =  9216   W2T chunk
#define OFF_B2   104448   // 64*4      =   256
#define SMEM_BYTES 104704

__device__ __forceinline__ uint32_t smem_u32(const void* p) {
    uint32_t a;
    asm("{ .reg .u64 t; cvta.to.shared.u64 t, %1; cvt.u32.u64 %0, t; }" : "=r"(a) : "l"(p));
    return a;
}
__device__ __forceinline__ void ldsm4(uint32_t& r0, uint32_t& r1, uint32_t& r2, uint32_t& r3,
                                      uint32_t addr) {
    asm volatile("ldmatrix.sync.aligned.m8n8.x4.shared.b16 {%0,%1,%2,%3}, [%4];"
        : "=r"(r0), "=r"(r1), "=r"(r2), "=r"(r3) : "r"(addr));
}
__device__ __forceinline__ void mma16816(float* c, uint32_t a0, uint32_t a1, uint32_t a2,
                                         uint32_t a3, uint32_t b0, uint32_t b1) {
    asm volatile(
        "mma.sync.aligned.m16n8k16.row.col.f32.f16.f16.f32 "
        "{%0,%1,%2,%3}, {%4,%5,%6,%7}, {%8,%9}, {%0,%1,%2,%3};"
        : "+f"(c[0]), "+f"(c[1]), "+f"(c[2]), "+f"(c[3])
        : "r"(a0), "r"(a1), "r"(a2), "r"(a3), "r"(b0), "r"(b1));
}
__device__ __forceinline__ float silu_f(float x) {
    return x * (1.f / (1.f + __expf(-x)));
}

// ---------------- prelude: A_q / A_k ----------------
__global__ void __launch_bounds__(256) prelude_kernel(
    const float* __restrict__ q_inv, const float* __restrict__ k_inv,
    const float* __restrict__ Wq, const float* __restrict__ bq,
    const float* __restrict__ Wk, const float* __restrict__ bk,
    const float* __restrict__ W1, const float* __restrict__ b1)
{
    int idx = blockIdx.x;
    bool isQ = idx < BB * NQ;
    int bn = isQ ? idx : idx - BB * NQ;

    const float* inv  = isQ ? (q_inv + bn * DINV) : (k_inv + bn * DINV);
    const float* W    = isQ ? Wq : Wk;
    const float* bias = isQ ? bq : bk;
    const float* W1s  = isQ ? W1 : (W1 + DMSG * DFF);
    float* A          = isQ ? (g_Aq + bn * DFF) : (g_Ak + bn * DFF);

    __shared__ float s_inv[DINV];
    __shared__ float s_part[4][DMSG];
    __shared__ float s_msg[DMSG];

    int tid = threadIdx.x;
    s_inv[tid] = inv[tid];
    __syncthreads();

    int m = tid & 63, g = tid >> 6;
    float acc = 0.f;
    #pragma unroll 8
    for (int i = g * 64; i < g * 64 + 64; i++)
        acc = fmaf(s_inv[i], W[i * DMSG + m], acc);
    s_part[g][m] = acc;
    __syncthreads();
    if (tid < DMSG)
        s_msg[tid] = s_part[0][tid] + s_part[1][tid] + s_part[2][tid] + s_part[3][tid] + bias[tid];
    __syncthreads();

    float a = isQ ? b1[tid] : 0.f;
    #pragma unroll 8
    for (int mm = 0; mm < DMSG; mm++)
        a = fmaf(s_msg[mm], W1s[mm * DFF + tid], a);
    A[tid] = a;
}

// ---------------- weight prep: transpose + fp16 ----------------
__global__ void __launch_bounds__(256) weight_prep_kernel(
    const float* __restrict__ W1, const float* __restrict__ W2)
{
    int idx = blockIdx.x * 256 + threadIdx.x;
    int total = DFF * 128 + DOUT * DFF;
    for (; idx < total; idx += gridDim.x * 256) {
        if (idx < DFF * 128) {
            int n = idx >> 7, k = idx & 127;              // W1T[n,k] = W1[128+k, n]
            g_W1T[n * LDA + k] = __float2half(W1[(128 + k) * DFF + n]);
        } else {
            int j = idx - DFF * 128;
            int n = j >> 8, k = j & 255;                  // W2T[n,k] = W2[k, n]
            g_W2T[n * 264 + k] = __float2half(W2[k * DOUT + n]);
        }
    }
}

// ---------------- main pairwise kernel ----------------
__global__ void __launch_bounds__(256) pair_kernel(
    const float* __restrict__ q_equi, const float* __restrict__ k_equi,
    const float* __restrict__ b2, float* __restrict__ out)
{
    extern __shared__ char smem[];
    const uint32_t sb = smem_u32(smem);
    int tid = threadIdx.x;
    int w = tid >> 5, lane = tid & 31;

    int b  = blockIdx.z;
    int q0 = blockIdx.y * TQ;
    int k0 = blockIdx.x * TK;

    __half* sA   = (__half*)(smem + OFF_SA);
    float*  sAq  = (float*)(smem + OFF_AQ);
    float*  sAk  = (float*)(smem + OFF_AK);
    __half* sW1c = (__half*)(smem + OFF_W1C);
    __half* sH   = (__half*)(smem + OFF_H);
    __half* sW2c = (__half*)(smem + OFF_W2C);
    float*  sb2  = (float*)(smem + OFF_B2);

    // ---- phase 0: stage equi (alias W1C/H), Aq/Ak, b2 ----
    {
        float* sqe = (float*)(smem + OFF_W1C);   // 16*192 floats = 12288 B
        float* ske = (float*)(smem + OFF_H);     //  8*192 floats =  6144 B
        const float4* q4 = (const float4*)(q_equi + (size_t)(b * NQ + q0) * 192);
        const float4* k4 = (const float4*)(k_equi + (size_t)(b * NK + k0) * 192);
        for (int i = tid; i < TQ * 48; i += 256) ((float4*)sqe)[i] = q4[i];
        for (int i = tid; i < TK * 48; i += 256) ((float4*)ske)[i] = k4[i];
        const float4* aq4 = (const float4*)(g_Aq + (size_t)(b * NQ + q0) * DFF);
        const float4* ak4 = (const float4*)(g_Ak + (size_t)(b * NK + k0) * DFF);
        for (int i = tid; i < TQ * 64; i += 256) ((float4*)sAq)[i] = aq4[i];
        for (int i = tid; i < TK * 64; i += 256) ((float4*)sAk)[i] = ak4[i];
        if (tid < 64) sb2[tid] = b2[tid];
        __syncthreads();

        // ---- phase 1: dot & dist -> sA fp16 [128][LDA] ----
        for (int idx = tid; idx < TM * 32; idx += 256) {
            int p = idx >> 5, e2 = (idx & 31) * 2;
            int qi = p >> 3, ki = p & 7;
            const float* qr = sqe + qi * 192 + e2;
            const float* kr = ske + ki * 192 + e2;
            float2 a0 = *(const float2*)(qr);
            float2 a1 = *(const float2*)(qr + 64);
            float2 a2 = *(const float2*)(qr + 128);
            float2 g0 = *(const float2*)(kr);
            float2 g1 = *(const float2*)(kr + 64);
            float2 g2 = *(const float2*)(kr + 128);
            float dx = a0.x * g0.x + a1.x * g1.x + a2.x * g2.x;
            float dy = a0.y * g0.y + a1.y * g1.y + a2.y * g2.y;
            float fx0 = a0.x - g0.x, fx1 = a1.x - g1.x, fx2 = a2.x - g2.x;
            float fy0 = a0.y - g0.y, fy1 = a1.y - g1.y, fy2 = a2.y - g2.y;
            float sx = sqrtf(fx0 * fx0 + fx1 * fx1 + fx2 * fx2);
            float sy = sqrtf(fy0 * fy0 + fy1 * fy1 + fy2 * fy2);
            *(__half2*)(sA + p * LDA + e2)      = __floats2half2_rn(dx, dy);
            *(__half2*)(sA + p * LDA + 64 + e2) = __floats2half2_rn(sx, sy);
        }
    }
    __syncthreads();

    // ---- ldmatrix lane address bases ----
    const int m0 = w * 16;
    // A/h operand: row = m0 + (lane&15), col-half-block = (lane>>4)*8
    const uint32_t aAddr1 = sb + OFF_SA + ((m0 + (lane & 15)) * LDA + (lane >> 4) * 8) * 2;
    const uint32_t aAddr2 = sb + OFF_H  + ((m0 + (lane & 15)) * LDH + (lane >> 4) * 8) * 2;
    // B operand: row = n-part, col-half-block = ((lane>>3)&1)*8
    const int bRow = (lane & 7) + ((lane >> 4) << 3);
    const uint32_t bAddr1 = sb + OFF_W1C + (bRow * LDA + ((lane >> 3) & 1) * 8) * 2;
    const uint32_t bAddr2 = sb + OFF_W2C + (bRow * LDH + ((lane >> 3) & 1) * 8) * 2;

    const int r = lane >> 2, cp = (lane & 3) * 2;
    const int m_lo = m0 + r, m_hi = m0 + r + 8;
    const int qi_lo = m_lo >> 3, ki_lo = m_lo & 7;
    const int qi_hi = m_hi >> 3, ki_hi = m_hi & 7;

    float acc2[8][4];
    #pragma unroll
    for (int j = 0; j < 8; j++)
        #pragma unroll
        for (int i = 0; i < 4; i++) acc2[j][i] = 0.f;

    // ================= chunk loop over N (4 x 64) =================
    for (int c = 0; c < 4; c++) {
        // ---- stage W1 chunk (contiguous 64 rows) + W2 chunk (strided) ----
        {
            const uint4* src = (const uint4*)(g_W1T + c * 64 * LDA);
            uint4* dst = (uint4*)sW1c;
            #pragma unroll
            for (int i = tid; i < 64 * LDA * 2 / 16; i += 256) dst[i] = src[i];
            for (int i = tid; i < 64 * 8; i += 256) {
                int row = i >> 3, seg = i & 7;
                *(uint4*)(sW2c + row * LDH + seg * 8) =
                    *(const uint4*)(g_W2T + row * 264 + c * 64 + seg * 8);
            }
        }
        __syncthreads();

        // ---- GEMM1 chunk: acc1[16,64] = A[16,128] @ W1c^T ----
        float acc1[8][4];
        #pragma unroll
        for (int j = 0; j < 8; j++)
            #pragma unroll
            for (int i = 0; i < 4; i++) acc1[j][i] = 0.f;

        #pragma unroll
        for (int kk = 0; kk < 8; kk++) {
            uint32_t a0, a1, a2, a3;
            ldsm4(a0, a1, a2, a3, aAddr1 + kk * 32);
            #pragma unroll
            for (int jp = 0; jp < 4; jp++) {
                uint32_t b0, b1, b2r, b3;
                ldsm4(b0, b1, b2r, b3, bAddr1 + jp * 16 * LDA * 2 + kk * 32);
                mma16816(acc1[2 * jp],     a0, a1, a2, a3, b0,  b1);
                mma16816(acc1[2 * jp + 1], a0, a1, a2, a3, b2r, b3);
            }
        }

        // ---- epilogue1: + Aq + Ak, SiLU, -> sH fp16 ----
        {
            const float* aqlo = sAq + qi_lo * DFF + c * 64;
            const float* aklo = sAk + ki_lo * DFF + c * 64;
            const float* aqhi = sAq + qi_hi * DFF + c * 64;
            const float* akhi = sAk + ki_hi * DFF + c * 64;
            #pragma unroll
            for (int j = 0; j < 8; j++) {
                int n = j * 8 + cp;
                float v0 = acc1[j][0] + aqlo[n]     + aklo[n];
                float v1 = acc1[j][1] + aqlo[n + 1] + aklo[n + 1];
                float v2 = acc1[j][2] + aqhi[n]     + akhi[n];
                float v3 = acc1[j][3] + aqhi[n + 1] + akhi[n + 1];
                *(__half2*)(sH + m_lo * LDH + n) = __floats2half2_rn(silu_f(v0), silu_f(v1));
                *(__half2*)(sH + m_hi * LDH + n) = __floats2half2_rn(silu_f(v2), silu_f(v3));
            }
        }
        __syncthreads();

        // ---- GEMM2 partial: acc2 += h[16,64] @ W2c^T ----
        #pragma unroll
        for (int kk = 0; kk < 4; kk++) {
            uint32_t a0, a1, a2, a3;
            ldsm4(a0, a1, a2, a3, aAddr2 + kk * 32);
            #pragma unroll
            for (int jp = 0; jp < 4; jp++) {
                uint32_t b0, b1, b2r, b3;
                ldsm4(b0, b1, b2r, b3, bAddr2 + jp * 16 * LDH * 2 + kk * 32);
                mma16816(acc2[2 * jp],     a0, a1, a2, a3, b0,  b1);
                mma16816(acc2[2 * jp + 1], a0, a1, a2, a3, b2r, b3);
            }
        }
        __syncthreads();   // before restaging W chunks / reusing sH
    }

    // ---- epilogue2: + b2, store ----
    {
        float* olo = out + ((size_t)(b * NQ + q0 + qi_lo) * NK + (k0 + ki_lo)) * DOUT;
        float* ohi = out + ((size_t)(b * NQ + q0 + qi_hi) * NK + (k0 + ki_hi)) * DOUT;
        #pragma unroll
        for (int j = 0; j < 8; j++) {
            int n = j * 8 + cp;
            float2 v0, v1;
            v0.x = acc2[j][0] + sb2[n];
            v0.y = acc2[j][1] + sb2[n + 1];
            v1.x = acc2[j][2] + sb2[n];
            v1.y = acc2[j][3] + sb2[n + 1];
            *(float2*)(olo + n) = v0;
            *(float2*)(ohi + n) = v1;
        }
    }
}

// ---------------------------------------------------------------------------
extern "C" void kernel_launch(void* const* d_in, const int* in_sizes, int n_in,
                              void* d_out, int out_size)
{
    const float* q_equi = (const float*)d_in[0];
    const float* q_inv  = (const float*)d_in[1];
    const float* k_equi = (const float*)d_in[2];
    const float* k_inv  = (const float*)d_in[3];
    const float* Wq     = (const float*)d_in[4];
    const float* bq     = (const float*)d_in[5];
    const float* Wk     = (const float*)d_in[6];
    const float* bk     = (const float*)d_in[7];
    const float* W1     = (const float*)d_in[8];
    const float* b1     = (const float*)d_in[9];
    const float* W2     = (const float*)d_in[10];
    const float* b2     = (const float*)d_in[11];
    float* out = (float*)d_out;

    cudaFuncSetAttribute(pair_kernel, cudaFuncAttributeMaxDynamicSharedMemorySize, SMEM_BYTES);

    prelude_kernel<<<BB * (NQ + NK), 256>>>(q_inv, k_inv, Wq, bq, Wk, bk, W1, b1);
    weight_prep_kernel<<<96, 256>>>(W1, W2);

    dim3 grid(NK / TK, NQ / TQ, BB);
    pair_kernel<<<grid, 256, SMEM_BYTES>>>(q_equi, k_equi, b2, out);
}

// round 4
// speedup vs baseline: 4.4257x; 1.0374x over previous
#include <cuda_runtime.h>
#include <cuda_fp16.h>
#include <cstdint>

// ---------------- problem constants ----------------
#define BB    4
#define NQ    384
#define NK    384
#define DE    64
#define DMSG  64
#define DFF   256
#define DOUT  64
#define DINV  256

#define TQ    16
#define TK    8
#define TM    128          // pairs per tile

#define LDA   136          // half pitch for A / W1 chunk tiles (k=128 + 8 pad)
#define LDH   72           // half pitch for h / W2 chunk tiles (k=64 + 8 pad)

#define NPRE  (BB * (NQ + NK))   // 3072 prelude blocks
#define NPREP 96                 // weight-prep blocks appended to prelude grid

// ---------------- device scratch ----------------
__device__ float g_Aq[BB * NQ * DFF];
__device__ float g_Ak[BB * NK * DFF];
__device__ __align__(16) __half g_W1T[DFF * LDA];   // [n=256][k pitch 136] fp16
__device__ __align__(16) __half g_W2T[DOUT * 264];  // [n=64][k pitch 264] fp16

// ---------------- SMEM map (bytes) ----------------
#define OFF_SA   0        // 128*136*2 = 34816   A (dot|dist) fp16
#define OFF_AQ   34816    // 16*256*4  = 16384   A_q fp32
#define OFF_AK   51200    //  8*256*4  =  8192   A_k fp32
#define OFF_W1C  59392    // 64*136*2  = 17408   W1T chunk (aliased: qe staging)
#define OFF_H    76800    // 128*72*2  = 18432   h chunk fp16 (aliased: ke staging)
#define OFF_W2C  95232    // 64*72*2   =  9216   W2T chunk
#define OFF_B2   104448   // 64*4      =   256
#define SMEM_BYTES 104704

__device__ __forceinline__ uint32_t smem_u32(const void* p) {
    uint32_t a;
    asm("{ .reg .u64 t; cvta.to.shared.u64 t, %1; cvt.u32.u64 %0, t; }" : "=r"(a) : "l"(p));
    return a;
}
__device__ __forceinline__ void ldsm4(uint32_t& r0, uint32_t& r1, uint32_t& r2, uint32_t& r3,
                                      uint32_t addr) {
    asm volatile("ldmatrix.sync.aligned.m8n8.x4.shared.b16 {%0,%1,%2,%3}, [%4];"
        : "=r"(r0), "=r"(r1), "=r"(r2), "=r"(r3) : "r"(addr));
}
__device__ __forceinline__ void mma16816(float* c, uint32_t a0, uint32_t a1, uint32_t a2,
                                         uint32_t a3, uint32_t b0, uint32_t b1) {
    asm volatile(
        "mma.sync.aligned.m16n8k16.row.col.f32.f16.f16.f32 "
        "{%0,%1,%2,%3}, {%4,%5,%6,%7}, {%8,%9}, {%0,%1,%2,%3};"
        : "+f"(c[0]), "+f"(c[1]), "+f"(c[2]), "+f"(c[3])
        : "r"(a0), "r"(a1), "r"(a2), "r"(a3), "r"(b0), "r"(b1));
}
__device__ __forceinline__ float silu_f(float x) {
    return x * (1.f / (1.f + __expf(-x)));
}

// ---------------- prelude: A_q / A_k (+ appended weight-prep blocks) ----------------
__global__ void __launch_bounds__(256) prelude_kernel(
    const float* __restrict__ q_inv, const float* __restrict__ k_inv,
    const float* __restrict__ Wq, const float* __restrict__ bq,
    const float* __restrict__ Wk, const float* __restrict__ bk,
    const float* __restrict__ W1, const float* __restrict__ b1,
    const float* __restrict__ W2)
{
    int blk = blockIdx.x;

    // ---- appended weight-prep blocks: transpose + fp16 ----
    if (blk >= NPRE) {
        int idx = (blk - NPRE) * 256 + threadIdx.x;
        int total = DFF * 128 + DOUT * DFF;
        for (; idx < total; idx += NPREP * 256) {
            if (idx < DFF * 128) {
                int n = idx >> 7, k = idx & 127;              // W1T[n,k] = W1[128+k, n]
                g_W1T[n * LDA + k] = __float2half(W1[(128 + k) * DFF + n]);
            } else {
                int j = idx - DFF * 128;
                int n = j >> 8, k = j & 255;                  // W2T[n,k] = W2[k, n]
                g_W2T[n * 264 + k] = __float2half(W2[k * DOUT + n]);
            }
        }
        return;
    }

    bool isQ = blk < BB * NQ;
    int bn = isQ ? blk : blk - BB * NQ;

    const float* inv  = isQ ? (q_inv + bn * DINV) : (k_inv + bn * DINV);
    const float* W    = isQ ? Wq : Wk;
    const float* bias = isQ ? bq : bk;
    const float* W1s  = isQ ? W1 : (W1 + DMSG * DFF);
    float* A          = isQ ? (g_Aq + bn * DFF) : (g_Ak + bn * DFF);

    __shared__ float s_inv[DINV];
    __shared__ float s_part[4][DMSG];
    __shared__ float s_msg[DMSG];

    int tid = threadIdx.x;
    s_inv[tid] = inv[tid];
    __syncthreads();

    int m = tid & 63, g = tid >> 6;
    float acc = 0.f;
    #pragma unroll 16
    for (int i = g * 64; i < g * 64 + 64; i++)
        acc = fmaf(s_inv[i], W[i * DMSG + m], acc);
    s_part[g][m] = acc;
    __syncthreads();
    if (tid < DMSG)
        s_msg[tid] = s_part[0][tid] + s_part[1][tid] + s_part[2][tid] + s_part[3][tid] + bias[tid];
    __syncthreads();

    float a = isQ ? b1[tid] : 0.f;
    #pragma unroll 32
    for (int mm = 0; mm < DMSG; mm++)
        a = fmaf(s_msg[mm], W1s[mm * DFF + tid], a);
    A[tid] = a;
}

// ---------------- main pairwise kernel (2 CTAs/SM) ----------------
__global__ void __launch_bounds__(256, 2) pair_kernel(
    const float* __restrict__ q_equi, const float* __restrict__ k_equi,
    const float* __restrict__ b2, float* __restrict__ out)
{
    extern __shared__ char smem[];
    const uint32_t sb = smem_u32(smem);
    int tid = threadIdx.x;
    int w = tid >> 5, lane = tid & 31;

    int b  = blockIdx.z;
    int q0 = blockIdx.y * TQ;
    int k0 = blockIdx.x * TK;

    __half* sA   = (__half*)(smem + OFF_SA);
    float*  sAq  = (float*)(smem + OFF_AQ);
    float*  sAk  = (float*)(smem + OFF_AK);
    __half* sW1c = (__half*)(smem + OFF_W1C);
    __half* sH   = (__half*)(smem + OFF_H);
    __half* sW2c = (__half*)(smem + OFF_W2C);
    float*  sb2  = (float*)(smem + OFF_B2);

    // ---- phase 0: stage equi (alias W1C/H), Aq/Ak, b2 ----
    {
        float* sqe = (float*)(smem + OFF_W1C);   // 16*192 floats
        float* ske = (float*)(smem + OFF_H);     //  8*192 floats
        const float4* q4 = (const float4*)(q_equi + (size_t)(b * NQ + q0) * 192);
        const float4* k4 = (const float4*)(k_equi + (size_t)(b * NK + k0) * 192);
        for (int i = tid; i < TQ * 48; i += 256) ((float4*)sqe)[i] = q4[i];
        for (int i = tid; i < TK * 48; i += 256) ((float4*)ske)[i] = k4[i];
        const float4* aq4 = (const float4*)(g_Aq + (size_t)(b * NQ + q0) * DFF);
        const float4* ak4 = (const float4*)(g_Ak + (size_t)(b * NK + k0) * DFF);
        for (int i = tid; i < TQ * 64; i += 256) ((float4*)sAq)[i] = aq4[i];
        for (int i = tid; i < TK * 64; i += 256) ((float4*)sAk)[i] = ak4[i];
        if (tid < 64) sb2[tid] = b2[tid];
        __syncthreads();

        // ---- phase 1: dot & dist -> sA fp16 [128][LDA] ----
        for (int idx = tid; idx < TM * 32; idx += 256) {
            int p = idx >> 5, e2 = (idx & 31) * 2;
            int qi = p >> 3, ki = p & 7;
            const float* qr = sqe + qi * 192 + e2;
            const float* kr = ske + ki * 192 + e2;
            float2 a0 = *(const float2*)(qr);
            float2 a1 = *(const float2*)(qr + 64);
            float2 a2 = *(const float2*)(qr + 128);
            float2 g0 = *(const float2*)(kr);
            float2 g1 = *(const float2*)(kr + 64);
            float2 g2 = *(const float2*)(kr + 128);
            float dx = a0.x * g0.x + a1.x * g1.x + a2.x * g2.x;
            float dy = a0.y * g0.y + a1.y * g1.y + a2.y * g2.y;
            float fx0 = a0.x - g0.x, fx1 = a1.x - g1.x, fx2 = a2.x - g2.x;
            float fy0 = a0.y - g0.y, fy1 = a1.y - g1.y, fy2 = a2.y - g2.y;
            float sx = sqrtf(fx0 * fx0 + fx1 * fx1 + fx2 * fx2);
            float sy = sqrtf(fy0 * fy0 + fy1 * fy1 + fy2 * fy2);
            *(__half2*)(sA + p * LDA + e2)      = __floats2half2_rn(dx, dy);
            *(__half2*)(sA + p * LDA + 64 + e2) = __floats2half2_rn(sx, sy);
        }
    }
    __syncthreads();

    // ---- ldmatrix lane address bases ----
    const int m0 = w * 16;
    const uint32_t aAddr1 = sb + OFF_SA + ((m0 + (lane & 15)) * LDA + (lane >> 4) * 8) * 2;
    const uint32_t aAddr2 = sb + OFF_H  + ((m0 + (lane & 15)) * LDH + (lane >> 4) * 8) * 2;
    const int bRow = (lane & 7) + ((lane >> 4) << 3);
    const uint32_t bAddr1 = sb + OFF_W1C + (bRow * LDA + ((lane >> 3) & 1) * 8) * 2;
    const uint32_t bAddr2 = sb + OFF_W2C + (bRow * LDH + ((lane >> 3) & 1) * 8) * 2;

    const int r = lane >> 2, cp = (lane & 3) * 2;
    const int m_lo = m0 + r, m_hi = m0 + r + 8;
    const int qi_lo = m_lo >> 3, ki_lo = m_lo & 7;
    const int qi_hi = m_hi >> 3, ki_hi = m_hi & 7;

    float acc2[8][4];
    #pragma unroll
    for (int j = 0; j < 8; j++)
        #pragma unroll
        for (int i = 0; i < 4; i++) acc2[j][i] = 0.f;

    // ================= chunk loop over N (4 x 64) =================
    for (int c = 0; c < 4; c++) {
        // ---- stage W1 chunk + W2 chunk ----
        {
            const uint4* src = (const uint4*)(g_W1T + c * 64 * LDA);
            uint4* dst = (uint4*)sW1c;
            #pragma unroll
            for (int i = tid; i < 64 * LDA * 2 / 16; i += 256) dst[i] = src[i];
            for (int i = tid; i < 64 * 8; i += 256) {
                int row = i >> 3, seg = i & 7;
                *(uint4*)(sW2c + row * LDH + seg * 8) =
                    *(const uint4*)(g_W2T + row * 264 + c * 64 + seg * 8);
            }
        }
        __syncthreads();

        // ---- GEMM1 chunk: acc1[16,64] = A[16,128] @ W1c^T ----
        float acc1[8][4];
        #pragma unroll
        for (int j = 0; j < 8; j++)
            #pragma unroll
            for (int i = 0; i < 4; i++) acc1[j][i] = 0.f;

        #pragma unroll
        for (int kk = 0; kk < 8; kk++) {
            uint32_t a0, a1, a2, a3;
            ldsm4(a0, a1, a2, a3, aAddr1 + kk * 32);
            #pragma unroll
            for (int jp = 0; jp < 4; jp++) {
                uint32_t b0, b1, b2r, b3;
                ldsm4(b0, b1, b2r, b3, bAddr1 + jp * 16 * LDA * 2 + kk * 32);
                mma16816(acc1[2 * jp],     a0, a1, a2, a3, b0,  b1);
                mma16816(acc1[2 * jp + 1], a0, a1, a2, a3, b2r, b3);
            }
        }

        // ---- epilogue1: + Aq + Ak, SiLU, -> sH fp16 (warp-private rows) ----
        {
            const float* aqlo = sAq + qi_lo * DFF + c * 64;
            const float* aklo = sAk + ki_lo * DFF + c * 64;
            const float* aqhi = sAq + qi_hi * DFF + c * 64;
            const float* akhi = sAk + ki_hi * DFF + c * 64;
            #pragma unroll
            for (int j = 0; j < 8; j++) {
                int n = j * 8 + cp;
                float v0 = acc1[j][0] + aqlo[n]     + aklo[n];
                float v1 = acc1[j][1] + aqlo[n + 1] + aklo[n + 1];
                float v2 = acc1[j][2] + aqhi[n]     + akhi[n];
                float v3 = acc1[j][3] + aqhi[n + 1] + akhi[n + 1];
                *(__half2*)(sH + m_lo * LDH + n) = __floats2half2_rn(silu_f(v0), silu_f(v1));
                *(__half2*)(sH + m_hi * LDH + n) = __floats2half2_rn(silu_f(v2), silu_f(v3));
            }
        }
        // each warp's GEMM2 A-fragments come only from its own 16 sH rows
        __syncwarp();

        // ---- GEMM2 partial: acc2 += h[16,64] @ W2c^T ----
        #pragma unroll
        for (int kk = 0; kk < 4; kk++) {
            uint32_t a0, a1, a2, a3;
            ldsm4(a0, a1, a2, a3, aAddr2 + kk * 32);
            #pragma unroll
            for (int jp = 0; jp < 4; jp++) {
                uint32_t b0, b1, b2r, b3;
                ldsm4(b0, b1, b2r, b3, bAddr2 + jp * 16 * LDH * 2 + kk * 32);
                mma16816(acc2[2 * jp],     a0, a1, a2, a3, b0,  b1);
                mma16816(acc2[2 * jp + 1], a0, a1, a2, a3, b2r, b3);
            }
        }
        __syncthreads();   // before restaging W chunks
    }

    // ---- epilogue2: + b2, store ----
    {
        float* olo = out + ((size_t)(b * NQ + q0 + qi_lo) * NK + (k0 + ki_lo)) * DOUT;
        float* ohi = out + ((size_t)(b * NQ + q0 + qi_hi) * NK + (k0 + ki_hi)) * DOUT;
        #pragma unroll
        for (int j = 0; j < 8; j++) {
            int n = j * 8 + cp;
            float2 v0, v1;
            v0.x = acc2[j][0] + sb2[n];
            v0.y = acc2[j][1] + sb2[n + 1];
            v1.x = acc2[j][2] + sb2[n];
            v1.y = acc2[j][3] + sb2[n + 1];
            *(float2*)(olo + n) = v0;
            *(float2*)(ohi + n) = v1;
        }
    }
}

// ---------------------------------------------------------------------------
extern "C" void kernel_launch(void* const* d_in, const int* in_sizes, int n_in,
                              void* d_out, int out_size)
{
    const float* q_equi = (const float*)d_in[0];
    const float* q_inv  = (const float*)d_in[1];
    const float* k_equi = (const float*)d_in[2];
    const float* k_inv  = (const float*)d_in[3];
    const float* Wq     = (const float*)d_in[4];
    const float* bq     = (const float*)d_in[5];
    const float* Wk     = (const float*)d_in[6];
    const float* bk     = (const float*)d_in[7];
    const float* W1     = (const float*)d_in[8];
    const float* b1     = (const float*)d_in[9];
    const float* W2     = (const float*)d_in[10];
    const float* b2     = (const float*)d_in[11];
    float* out = (float*)d_out;

    cudaFuncSetAttribute(pair_kernel, cudaFuncAttributeMaxDynamicSharedMemorySize, SMEM_BYTES);

    prelude_kernel<<<NPRE + NPREP, 256>>>(q_inv, k_inv, Wq, bq, Wk, bk, W1, b1, W2);

    dim3 grid(NK / TK, NQ / TQ, BB);
    pair_kernel<<<grid, 256, SMEM_BYTES>>>(q_equi, k_equi, b2, out);
}